// round 16
// baseline (speedup 1.0000x reference)
#include <cuda_runtime.h>
#include <cuda_fp16.h>

#define N_NODES 100000
#define N_EDGES 1600000
#define IN_DIM  128
#define OUT_DIM 64
#define NEG_SLOPE 0.2f

#define SCAN_B 1024
#define SCAN_NB ((N_NODES + SCAN_B - 1) / SCAN_B)   // 98
#define GEMM_BLOCKS ((N_NODES + 127) / 128)         // 782
#define HIST_BLOCKS ((N_EDGES / 4 + 255) / 256)     // 1563
#define TOTAL_BLOCKS (GEMM_BLOCKS * 3)              // 2346 (1:2 interleave)

// Scratch (static device globals — zero-init at load; g_count self-cleaning)
__device__ __align__(16) __half g_Whh[(size_t)N_NODES * OUT_DIM];
__device__ float g_ssrc[N_NODES];
__device__ float g_sdst[N_NODES];
__device__ int   g_count[N_NODES];     // agg zeroes after use
__device__ int   g_rowstart[N_NODES];
__device__ int   g_bsum[SCAN_NB];
__device__ __align__(8) unsigned short g_eoff[N_EDGES];  // within-row rank
__device__ int   g_ecol[N_EDGES];      // col indices grouped by row

// ---------------------------------------------------------------------------
// mma.sync m16n8k16 f16f16f32 (row.col). Standard sm_80+ fragment layout.
// ---------------------------------------------------------------------------
__device__ __forceinline__ void mma16816(float& d0, float& d1, float& d2, float& d3,
                                         unsigned a0, unsigned a1, unsigned a2, unsigned a3,
                                         unsigned b0, unsigned b1) {
    asm volatile(
        "mma.sync.aligned.m16n8k16.row.col.f32.f16.f16.f32 "
        "{%0,%1,%2,%3}, {%4,%5,%6,%7}, {%8,%9}, {%0,%1,%2,%3};"
        : "+f"(d0), "+f"(d1), "+f"(d2), "+f"(d3)
        : "r"(a0), "r"(a1), "r"(a2), "r"(a3), "r"(b0), "r"(b1));
}

// ---------------------------------------------------------------------------
// K1: role-split (1 GEMM : 2 hist interleave). GEMM: tensor-core Wh = h@W,
// 128 rows x 64 cols per block, fp16 inputs / f32 accum; f32 scores via
// s = h @ (W@a) computed from the f32 h tiles during load.
// ---------------------------------------------------------------------------
__global__ void gemm_hist_kernel(const float* __restrict__ h,
                                 const float* __restrict__ W,
                                 const float* __restrict__ a,
                                 const int*   __restrict__ row) {
    const int tid = threadIdx.x;
    const int mod = blockIdx.x % 3;

    if (mod != 0) {
        // ---- histogram + rank role: 4 edges per thread ----
        int hb = (blockIdx.x / 3) * 2 + (mod - 1);
        if (hb >= HIST_BLOCKS) return;
        int t = hb * blockDim.x + tid;
        if (t * 4 < N_EDGES) {
            int4 r = ((const int4*)row)[t];
            unsigned int o0 = (unsigned int)atomicAdd(&g_count[r.x], 1);
            unsigned int o1 = (unsigned int)atomicAdd(&g_count[r.y], 1);
            unsigned int o2 = (unsigned int)atomicAdd(&g_count[r.z], 1);
            unsigned int o3 = (unsigned int)atomicAdd(&g_count[r.w], 1);
            uint2 pk;
            pk.x = (o0 & 0xFFFFu) | (o1 << 16);
            pk.y = (o2 & 0xFFFFu) | (o3 << 16);
            ((uint2*)g_eoff)[t] = pk;
        }
        return;
    }

    // ---- GEMM role ----
    __shared__ __align__(16) __half hs[128][72];   // h chunk fp16 (stride 72 halfs)
    __shared__ __align__(16) __half Ws[64][72];    // W^T chunk fp16 [n][k]
    __shared__ float u_src[128], u_dst[128];
    __shared__ float a_sh[128];

    const int g    = blockIdx.x / 3;
    const int row0 = g * 128;
    const int lane = tid & 31;
    const int wrp  = tid >> 5;

    if (tid < 128) a_sh[tid] = a[tid];
    __syncthreads();

    // u = W @ a_src / a_dst  (f32, per block; W is L2-hot 32KB)
    if (tid < 128) {
        float us = 0.f, ud = 0.f;
        const float4* W4 = (const float4*)W;
        #pragma unroll 16
        for (int i = 0; i < 16; i++) {
            float4 w4 = W4[tid * 16 + i];
            us += w4.x * a_sh[i*4+0] + w4.y * a_sh[i*4+1]
                + w4.z * a_sh[i*4+2] + w4.w * a_sh[i*4+3];
            ud += w4.x * a_sh[64+i*4+0] + w4.y * a_sh[64+i*4+1]
                + w4.z * a_sh[64+i*4+2] + w4.w * a_sh[64+i*4+3];
        }
        u_src[tid] = us; u_dst[tid] = ud;
    }
    __syncthreads();

    float acc[8][4];
    #pragma unroll
    for (int nt = 0; nt < 8; nt++)
        #pragma unroll
        for (int j = 0; j < 4; j++) acc[nt][j] = 0.f;

    // score partials: thread covers row r = tid>>1, cols 32*(tid&1)..+31 per chunk
    const int srow = tid >> 1;
    const int scb  = (tid & 1) * 8;       // float4 base within chunk
    float ssp = 0.f, sdp = 0.f;

    const int r0 = wrp * 16 + (lane >> 2);
    const int k0 = (lane & 3) * 2;

    #pragma unroll
    for (int kc = 0; kc < 2; kc++) {
        // load h chunk (f32), convert to fp16, accumulate score partials
        {
            int node = row0 + srow;
            #pragma unroll
            for (int p = 0; p < 8; p++) {
                float4 v = make_float4(0.f, 0.f, 0.f, 0.f);
                if (node < N_NODES)
                    v = ((const float4*)h)[(size_t)node * 32 + kc * 16 + scb + p];
                int colb = (scb + p) * 4;
                *(__half2*)&hs[srow][colb]     = __floats2half2_rn(v.x, v.y);
                *(__half2*)&hs[srow][colb + 2] = __floats2half2_rn(v.z, v.w);
                int ub = kc * 64 + colb;
                ssp += v.x * u_src[ub] + v.y * u_src[ub+1] + v.z * u_src[ub+2] + v.w * u_src[ub+3];
                sdp += v.x * u_dst[ub] + v.y * u_dst[ub+1] + v.z * u_dst[ub+2] + v.w * u_dst[ub+3];
            }
        }
        // load W chunk transposed: Ws[n][k]
        #pragma unroll
        for (int p = 0; p < 4; p++) {
            int idx = tid + p * 256;          // < 1024
            int k = idx >> 4, n4 = idx & 15;
            float4 wv = ((const float4*)W)[(size_t)(kc * 64 + k) * 16 + n4];
            Ws[n4*4+0][k] = __float2half(wv.x);
            Ws[n4*4+1][k] = __float2half(wv.y);
            Ws[n4*4+2][k] = __float2half(wv.z);
            Ws[n4*4+3][k] = __float2half(wv.w);
        }
        __syncthreads();

        // 4 k16 steps of mma over this 64-wide chunk
        #pragma unroll
        for (int ks = 0; ks < 4; ks++) {
            int kb = ks * 16;
            unsigned a0 = *(const unsigned*)&hs[r0    ][kb + k0];
            unsigned a1 = *(const unsigned*)&hs[r0 + 8][kb + k0];
            unsigned a2 = *(const unsigned*)&hs[r0    ][kb + k0 + 8];
            unsigned a3 = *(const unsigned*)&hs[r0 + 8][kb + k0 + 8];
            #pragma unroll
            for (int nt = 0; nt < 8; nt++) {
                int n = nt * 8 + (lane >> 2);
                unsigned b0 = *(const unsigned*)&Ws[n][kb + k0];
                unsigned b1 = *(const unsigned*)&Ws[n][kb + k0 + 8];
                mma16816(acc[nt][0], acc[nt][1], acc[nt][2], acc[nt][3],
                         a0, a1, a2, a3, b0, b1);
            }
        }
        __syncthreads();
    }

    // scores: combine thread pairs (t even + t odd cover the full row)
    {
        float ss = ssp + __shfl_down_sync(0xFFFFFFFFu, ssp, 1);
        float sd = sdp + __shfl_down_sync(0xFFFFFFFFu, sdp, 1);
        int node = row0 + srow;
        if ((tid & 1) == 0 && node < N_NODES) {
            g_ssrc[node] = ss;
            g_sdst[node] = sd;
        }
    }

    // epilogue: write Wh as fp16 (d0,d1 = adjacent cols -> one half2 store)
    {
        int colb = (lane & 3) * 2;
        int ra = row0 + r0;        // rows r0 and r0+8
        #pragma unroll
        for (int nt = 0; nt < 8; nt++) {
            int c = nt * 8 + colb;
            if (ra < N_NODES)
                *(__half2*)&g_Whh[(size_t)ra * 64 + c] =
                    __floats2half2_rn(acc[nt][0], acc[nt][1]);
            if (ra + 8 < N_NODES)
                *(__half2*)&g_Whh[(size_t)(ra + 8) * 64 + c] =
                    __floats2half2_rn(acc[nt][2], acc[nt][3]);
        }
    }
}

// ---------------------------------------------------------------------------
// K2: block-local exclusive scan of g_count -> g_rowstart, block sums in bsum
// ---------------------------------------------------------------------------
__global__ void scan1_kernel() {
    __shared__ int s[SCAN_B];
    int i = blockIdx.x * SCAN_B + threadIdx.x;
    int v = (i < N_NODES) ? g_count[i] : 0;
    s[threadIdx.x] = v;
    __syncthreads();
    int x = v;
    #pragma unroll
    for (int o = 1; o < SCAN_B; o <<= 1) {
        int t = (threadIdx.x >= o) ? s[threadIdx.x - o] : 0;
        __syncthreads();
        x += t;
        s[threadIdx.x] = x;
        __syncthreads();
    }
    if (i < N_NODES) g_rowstart[i] = x - v;
    if (threadIdx.x == SCAN_B - 1) g_bsum[blockIdx.x] = x;
}

// ---------------------------------------------------------------------------
// K3: add bsum prefix to rowstart
// ---------------------------------------------------------------------------
__global__ void scan3_kernel() {
    __shared__ int warp_part[4];
    __shared__ int s_prefix;
    const int b = blockIdx.x;
    const int t = threadIdx.x;

    if (t < 128) {
        int v = (t < b) ? g_bsum[t] : 0;     // b <= 97 < 128
        #pragma unroll
        for (int o = 16; o > 0; o >>= 1)
            v += __shfl_down_sync(0xFFFFFFFFu, v, o);
        if ((t & 31) == 0) warp_part[t >> 5] = v;
    }
    __syncthreads();
    if (t == 0)
        s_prefix = warp_part[0] + warp_part[1] + warp_part[2] + warp_part[3];
    __syncthreads();

    int i = b * SCAN_B + t;
    if (i < N_NODES)
        g_rowstart[i] += s_prefix;
}

// ---------------------------------------------------------------------------
// K4: atomic-free scatter: ecol[rowstart[r] + eoff[e]] = c. 4 edges/thread.
// ---------------------------------------------------------------------------
__global__ void scatter_kernel(const int* __restrict__ row,
                               const int* __restrict__ col) {
    int t = blockIdx.x * blockDim.x + threadIdx.x;
    if (t * 4 >= N_EDGES) return;
    int4 r = ((const int4*)row)[t];
    int4 c = ((const int4*)col)[t];
    uint2 ePk = ((const uint2*)g_eoff)[t];
    int rr[4] = {r.x, r.y, r.z, r.w};
    int cc[4] = {c.x, c.y, c.z, c.w};
    int oo[4] = {(int)(ePk.x & 0xFFFFu), (int)(ePk.x >> 16),
                 (int)(ePk.y & 0xFFFFu), (int)(ePk.y >> 16)};
    int st[4];
    #pragma unroll
    for (int j = 0; j < 4; j++) st[j] = __ldg(&g_rowstart[rr[j]]);
    #pragma unroll
    for (int j = 0; j < 4; j++) g_ecol[st[j] + oo[j]] = cc[j];
}

// ---------------------------------------------------------------------------
// K5: per-node aggregation, 4 edges per step via quarter-warp split.
// Lane qid=lane>>3 picks the edge slot, ql=lane&7 picks 8 columns loaded as
// one uint4 (LDG.128). Halves the dependent-step count vs the half-warp
// version and doubles in-flight load width. Unnormalized accumulation,
// scaled by 1/denom at the end; quarters combined via shfl_xor(8,16).
// ---------------------------------------------------------------------------
__global__ void agg_csr_kernel(float* __restrict__ out) {
    const int warp = (blockIdx.x * blockDim.x + threadIdx.x) >> 5;
    const int lane = threadIdx.x & 31;
    if (warp >= N_NODES) return;

    const int start = g_rowstart[warp];
    const int cnt   = g_count[warp];
    const float ssr = g_ssrc[warp];

    const int qid = lane >> 3;     // edge slot within a 4-edge step
    const int ql  = lane & 7;      // 8-half column group

    const uint4* Wh8 = (const uint4*)g_Whh;   // 8 uint4 per 64-half row
    float acc[8];
    #pragma unroll
    for (int i = 0; i < 8; i++) acc[i] = 0.f;
    float dsum = 0.f;

    for (int base = 0; base < cnt; base += 32) {
        int idx = base + lane;
        int c_lane = 0;
        float w_lane = 0.f;
        if (idx < cnt) {
            c_lane = __ldg(&g_ecol[start + idx]);
            float x = ssr + __ldg(&g_sdst[c_lane]);
            x = (x > 0.f) ? x : NEG_SLOPE * x;
            w_lane = __expf(x);
        }
        dsum += w_lane;
        int m = cnt - base; if (m > 32) m = 32;
        int nsteps = (m + 3) >> 2;
        #pragma unroll 4
        for (int j = 0; j < nsteps; j++) {
            int src = j * 4 + qid;               // padded lanes have w=0
            int   c = __shfl_sync(0xFFFFFFFFu, c_lane, src);
            float w = __shfl_sync(0xFFFFFFFFu, w_lane, src);
            uint4 raw = __ldg(&Wh8[(size_t)c * 8 + ql]);
            float2 v0 = __half22float2(*(const __half2*)&raw.x);
            float2 v1 = __half22float2(*(const __half2*)&raw.y);
            float2 v2 = __half22float2(*(const __half2*)&raw.z);
            float2 v3 = __half22float2(*(const __half2*)&raw.w);
            acc[0] = fmaf(w, v0.x, acc[0]);
            acc[1] = fmaf(w, v0.y, acc[1]);
            acc[2] = fmaf(w, v1.x, acc[2]);
            acc[3] = fmaf(w, v1.y, acc[3]);
            acc[4] = fmaf(w, v2.x, acc[4]);
            acc[5] = fmaf(w, v2.y, acc[5]);
            acc[6] = fmaf(w, v3.x, acc[6]);
            acc[7] = fmaf(w, v3.y, acc[7]);
        }
    }

    // full-warp denominator
    #pragma unroll
    for (int o = 16; o > 0; o >>= 1)
        dsum += __shfl_xor_sync(0xFFFFFFFFu, dsum, o);
    const float inv = 1.f / (dsum + 1e-10f);

    // combine the 4 quarter-partials (lanes with equal ql)
    #pragma unroll
    for (int i = 0; i < 8; i++) {
        acc[i] += __shfl_xor_sync(0xFFFFFFFFu, acc[i], 8);
        acc[i] += __shfl_xor_sync(0xFFFFFFFFu, acc[i], 16);
    }

    if (qid == 0) {
        float4 lo = make_float4(acc[0]*inv, acc[1]*inv, acc[2]*inv, acc[3]*inv);
        float4 hi = make_float4(acc[4]*inv, acc[5]*inv, acc[6]*inv, acc[7]*inv);
        ((float4*)out)[(size_t)warp * 16 + ql * 2]     = lo;
        ((float4*)out)[(size_t)warp * 16 + ql * 2 + 1] = hi;
    }

    if (lane == 0) g_count[warp] = 0;   // self-clean for next replay
}

// ---------------------------------------------------------------------------
extern "C" void kernel_launch(void* const* d_in, const int* in_sizes, int n_in,
                              void* d_out, int out_size) {
    const float* h   = (const float*)d_in[0];
    const int*   row = (const int*)d_in[1];
    const int*   col = (const int*)d_in[2];
    const float* W   = (const float*)d_in[3];
    const float* a   = (const float*)d_in[4];
    float*       out = (float*)d_out;

    gemm_hist_kernel<<<TOTAL_BLOCKS, 256>>>(h, W, a, row);
    scan1_kernel<<<SCAN_NB, SCAN_B>>>();
    scan3_kernel<<<SCAN_NB, SCAN_B>>>();
    scatter_kernel<<<(N_EDGES / 4 + 255) / 256, 256>>>(row, col);
    agg_csr_kernel<<<(N_NODES * 32 + 255) / 256, 256>>>(out);
}